// round 2
// baseline (speedup 1.0000x reference)
#include <cuda_runtime.h>
#include <cuda_bf16.h>

#define DEVI static __device__ __forceinline__

// ---------------- problem dims ----------------
constexpr int BN   = 2048;   // BS * N_AGENTS
constexpr int LN   = 12;     // MAX_LANES
constexpr int LD   = 27;     // LANE_DIM
constexpr int H    = 128;    // HID
constexpr int NB   = 8;      // BS
constexpr int NA   = 256;    // N_AGENTS
constexpr int NACT = 8;
constexpr int G3   = 3 * H;  // 384

// ---------------- scratch (no cudaMalloc allowed) ----------------
__device__ float g_agg[BN * H];
__device__ float g_hg [BN * H];
__device__ float g_ai [BN * H];   // a_i with ga1_b folded in
__device__ float g_aj [BN * H];
__device__ float g_aw [NB * NA * NA];

// ---------------- packed f32x2 helpers ----------------
DEVI unsigned long long pk2(float a, float b) {
    unsigned long long r;
    asm("mov.b64 %0, {%1, %2};" : "=l"(r) : "f"(a), "f"(b));
    return r;
}
DEVI unsigned long long f2fma(unsigned long long a, unsigned long long b, unsigned long long c) {
    unsigned long long d;
    asm("fma.rn.f32x2 %0, %1, %2, %3;" : "=l"(d) : "l"(a), "l"(b), "l"(c));
    return d;
}
DEVI float2 up2(unsigned long long v) {
    float lo, hi;
    asm("mov.b64 {%0, %1}, %2;" : "=f"(lo), "=f"(hi) : "l"(v));
    return make_float2(lo, hi);
}

// acc[NR/2] packed pairs over NR rows; xrow = transposed activations, 16B aligned
template<int NR>
DEVI void gemv_step(const float* __restrict__ xrow, float w, unsigned long long* acc) {
    unsigned long long ww = pk2(w, w);
    const ulonglong2* xp = reinterpret_cast<const ulonglong2*>(xrow);
#pragma unroll
    for (int q = 0; q < NR / 4; q++) {
        ulonglong2 xv = xp[q];
        acc[2 * q]     = f2fma(xv.x, ww, acc[2 * q]);
        acc[2 * q + 1] = f2fma(xv.y, ww, acc[2 * q + 1]);
    }
}

DEVI float sigm(float x) { return 1.0f / (1.0f + expf(-x)); }

// ============================================================================
// K1: lane encoder. 4 agents (48 lane-rows) per block, 384 threads.
// fc1+relu -> gi (and gh unless h_in tile is all-zero) -> GRU gates ->
// lane-attention softmax -> aggregated (BN,H)
// ============================================================================
constexpr int KA_BNPB = 4;
constexpr int KA_R    = KA_BNPB * LN;   // 48
constexpr int KA_T    = 384;
constexpr int KA_P    = 52;             // xT/hinT pitch (words): 16B-aligned rows, 4-way max conflict

struct KAS {
    float lf[KA_R][28];      //   5376 B
    float xT[H][KA_P];       //  26624 B  (x transposed; later overwritten with h)
    float hinT[H][KA_P];     //  26624 B
    float gi[KA_R][G3];      //  73728 B
    float gh[KA_R][G3];      //  73728 B
    float sc[KA_R];
    float ps[KA_R];
};

__global__ __launch_bounds__(KA_T, 1)
void k_lane(const float* __restrict__ lf, const float* __restrict__ hid,
            const float* __restrict__ fc1_w, const float* __restrict__ fc1_b,
            const float* __restrict__ w_ih, const float* __restrict__ w_hh,
            const float* __restrict__ b_ih, const float* __restrict__ b_hh,
            const float* __restrict__ law, const float* __restrict__ lab)
{
    extern __shared__ float smem_raw[];
    KAS& s = *reinterpret_cast<KAS*>(smem_raw);
    const int t  = threadIdx.x;
    const int R0 = blockIdx.x * KA_R;   // global lane-row base

    for (int idx = t; idx < KA_R * LD; idx += KA_T) {
        int r = idx / LD, d = idx % LD;
        s.lf[r][d] = lf[(R0 + r) * LD + d];
    }
    bool nz = false;
    for (int idx = t; idx < KA_R * H; idx += KA_T) {
        int r = idx >> 7, h = idx & 127;
        float v = hid[(R0 + r) * H + h];
        nz |= (v != 0.0f);
        s.hinT[h][r] = v;
    }
    const int any = __syncthreads_or((int)nz);

    // x = relu(lf @ fc1^T + b)  -> xT[h][r]
    for (int idx = t; idx < H * KA_R; idx += KA_T) {
        int h = idx / KA_R, r = idx % KA_R;
        float acc = fc1_b[h];
        const float* wr = fc1_w + h * LD;
#pragma unroll
        for (int d = 0; d < LD; d++) acc += s.lf[r][d] * wr[d];
        s.xT[h][r] = fmaxf(acc, 0.0f);
    }
    __syncthreads();

    // gi = x @ w_ih^T : thread t = gate-row g, all 48 rows live in packed regs
    {
        const int g = t;
        unsigned long long acc[KA_R / 2];
#pragma unroll
        for (int q = 0; q < KA_R / 2; q++) acc[q] = 0ull;
        const float* wr = w_ih + g * H;
#pragma unroll 1
        for (int h = 0; h < H; h += 4) {
            float4 w4 = *reinterpret_cast<const float4*>(wr + h);
            gemv_step<KA_R>(&s.xT[h + 0][0], w4.x, acc);
            gemv_step<KA_R>(&s.xT[h + 1][0], w4.y, acc);
            gemv_step<KA_R>(&s.xT[h + 2][0], w4.z, acc);
            gemv_step<KA_R>(&s.xT[h + 3][0], w4.w, acc);
        }
#pragma unroll
        for (int q = 0; q < KA_R / 2; q++) {
            float2 f = up2(acc[q]);
            s.gi[2 * q][g]     = f.x;
            s.gi[2 * q + 1][g] = f.y;
        }
    }
    // gh = h_in @ w_hh^T — skipped when this block's h_in tile is all-zero
    if (any) {
        const int g = t;
        unsigned long long acc[KA_R / 2];
#pragma unroll
        for (int q = 0; q < KA_R / 2; q++) acc[q] = 0ull;
        const float* wr = w_hh + g * H;
#pragma unroll 1
        for (int h = 0; h < H; h += 4) {
            float4 w4 = *reinterpret_cast<const float4*>(wr + h);
            gemv_step<KA_R>(&s.hinT[h + 0][0], w4.x, acc);
            gemv_step<KA_R>(&s.hinT[h + 1][0], w4.y, acc);
            gemv_step<KA_R>(&s.hinT[h + 2][0], w4.z, acc);
            gemv_step<KA_R>(&s.hinT[h + 3][0], w4.w, acc);
        }
#pragma unroll
        for (int q = 0; q < KA_R / 2; q++) {
            float2 f = up2(acc[q]);
            s.gh[2 * q][g]     = f.x;
            s.gh[2 * q + 1][g] = f.y;
        }
    }
    __syncthreads();

    // GRU gates -> h (stored over xT)
    for (int idx = t; idx < KA_R * H; idx += KA_T) {
        int r = idx >> 7, h = idx & 127;
        float gir = s.gi[r][h]         + b_ih[h];
        float giz = s.gi[r][H + h]     + b_ih[H + h];
        float gin = s.gi[r][2 * H + h] + b_ih[2 * H + h];
        float ghr = b_hh[h], ghz = b_hh[H + h], ghn = b_hh[2 * H + h];
        if (any) {
            ghr += s.gh[r][h];
            ghz += s.gh[r][H + h];
            ghn += s.gh[r][2 * H + h];
        }
        float rr = sigm(gir + ghr);
        float zz = sigm(giz + ghz);
        float nn = tanhf(gin + rr * ghn);
        s.xT[h][r] = (1.0f - zz) * nn + zz * s.hinT[h][r];
    }
    __syncthreads();

    // lane-attention scores: warp w handles rows 4w..4w+3 (155-dim dot, shuffle reduce)
    {
        const int wid = t >> 5, lane = t & 31;
        const float lb = lab[0];
        for (int r = wid * 4; r < wid * 4 + 4; r++) {
            float acc = 0.0f;
            if (lane < LD) acc = s.lf[r][lane] * law[lane];
#pragma unroll
            for (int h = lane; h < H; h += 32) acc += s.xT[h][r] * law[LD + h];
#pragma unroll
            for (int o = 16; o; o >>= 1) acc += __shfl_xor_sync(0xffffffffu, acc, o);
            if (lane == 0) s.sc[r] = acc + lb;
        }
    }
    __syncthreads();
    if (t < KA_R) {
        int bl = t / LN;
        float m = -1e30f;
#pragma unroll
        for (int l = 0; l < LN; l++) m = fmaxf(m, s.sc[bl * LN + l]);
        float sum = 0.0f;
#pragma unroll
        for (int l = 0; l < LN; l++) sum += expf(s.sc[bl * LN + l] - m);
        s.ps[t] = expf(s.sc[t] - m) / sum;
    }
    __syncthreads();
    // aggregated[h] = sum_l p_l * h[l][h]
    for (int idx = t; idx < KA_BNPB * H; idx += KA_T) {
        int bl = idx >> 7, h = idx & 127;
        float acc = 0.0f;
#pragma unroll
        for (int l = 0; l < LN; l++) acc += s.ps[bl * LN + l] * s.xT[h][bl * LN + l];
        g_agg[(blockIdx.x * KA_BNPB + bl) * H + h] = acc;
    }
}

// ============================================================================
// K2: hg = agg@gfc^T + b ; a_i = hg@A^T + ga1_b ; a_j = hg@B^T
// 16 agent-rows per block, 128 threads (thread = output channel)
// ============================================================================
constexpr int KB_R = 16;
constexpr int KB_P = 20;  // row pitch (words): 16B-aligned, 4-way max conflict

__global__ __launch_bounds__(128)
void k_graphproj(const float* __restrict__ gfc_w, const float* __restrict__ gfc_b,
                 const float* __restrict__ ga1_w, const float* __restrict__ ga1_b)
{
    __shared__ float aggT[H][KB_P];
    __shared__ float hgT[H][KB_P];
    const int t  = threadIdx.x;
    const int r0 = blockIdx.x * KB_R;

    for (int idx = t; idx < KB_R * H; idx += 128) {
        int r = idx >> 7, h = idx & 127;
        aggT[h][r] = g_agg[(r0 + r) * H + h];
    }
    __syncthreads();
    {
        unsigned long long acc[KB_R / 2];
#pragma unroll
        for (int q = 0; q < KB_R / 2; q++) acc[q] = 0ull;
        const float* wr = gfc_w + t * H;
#pragma unroll 1
        for (int h = 0; h < H; h += 4) {
            float4 w4 = *reinterpret_cast<const float4*>(wr + h);
            gemv_step<KB_R>(&aggT[h + 0][0], w4.x, acc);
            gemv_step<KB_R>(&aggT[h + 1][0], w4.y, acc);
            gemv_step<KB_R>(&aggT[h + 2][0], w4.z, acc);
            gemv_step<KB_R>(&aggT[h + 3][0], w4.w, acc);
        }
        float bias = gfc_b[t];
#pragma unroll
        for (int q = 0; q < KB_R / 2; q++) {
            float2 f = up2(acc[q]);
            float v0 = f.x + bias, v1 = f.y + bias;
            hgT[t][2 * q]     = v0;
            hgT[t][2 * q + 1] = v1;
            g_hg[(r0 + 2 * q) * H + t]     = v0;
            g_hg[(r0 + 2 * q + 1) * H + t] = v1;
        }
    }
    __syncthreads();
    {
        unsigned long long accA[KB_R / 2], accB[KB_R / 2];
#pragma unroll
        for (int q = 0; q < KB_R / 2; q++) { accA[q] = 0ull; accB[q] = 0ull; }
        const float* wa = ga1_w + t * (2 * H);
        const float* wb = wa + H;
#pragma unroll 1
        for (int h = 0; h < H; h += 4) {
            float4 a4 = *reinterpret_cast<const float4*>(wa + h);
            float4 b4 = *reinterpret_cast<const float4*>(wb + h);
            gemv_step<KB_R>(&hgT[h + 0][0], a4.x, accA);
            gemv_step<KB_R>(&hgT[h + 0][0], b4.x, accB);
            gemv_step<KB_R>(&hgT[h + 1][0], a4.y, accA);
            gemv_step<KB_R>(&hgT[h + 1][0], b4.y, accB);
            gemv_step<KB_R>(&hgT[h + 2][0], a4.z, accA);
            gemv_step<KB_R>(&hgT[h + 2][0], b4.z, accB);
            gemv_step<KB_R>(&hgT[h + 3][0], a4.w, accA);
            gemv_step<KB_R>(&hgT[h + 3][0], b4.w, accB);
        }
        float ba = ga1_b[t];
#pragma unroll
        for (int q = 0; q < KB_R / 2; q++) {
            float2 fa = up2(accA[q]);
            float2 fb = up2(accB[q]);
            g_ai[(r0 + 2 * q) * H + t]     = fa.x + ba;
            g_ai[(r0 + 2 * q + 1) * H + t] = fa.y + ba;
            g_aj[(r0 + 2 * q) * H + t]     = fb.x;
            g_aj[(r0 + 2 * q + 1) * H + t] = fb.y;
        }
    }
}

// ============================================================================
// K3: e[b,i,j] = sum_h relu(ai+aj)*w2 + b2, adj-mask, softmax over j
// One (batch, 16-i-tile) per block; full a_j[b] slab resident in smem.
// 256 threads (thread = j). Pitch 132 words: conflict-free float4 rows.
// ============================================================================
constexpr int KC_IT = 16;
constexpr int KC_P  = 132;

struct KCS {
    float aj[NA * KC_P];     // [j][h]  135168 B
    float ai[KC_IT * KC_P];  // [ii][h]   8448 B
    float w2[H];
    float redm[8];
    float reds[8];
};

__global__ __launch_bounds__(256, 1)
void k_edge(const float* __restrict__ adj, const float* __restrict__ ga2_w,
            const float* __restrict__ ga2_b)
{
    extern __shared__ float smem_raw[];
    KCS& s = *reinterpret_cast<KCS*>(smem_raw);
    const int t  = threadIdx.x;
    const int b  = blockIdx.y;
    const int i0 = blockIdx.x * KC_IT;

    for (int idx = t; idx < NA * H; idx += 256) {
        int j = idx >> 7, h = idx & 127;
        s.aj[j * KC_P + h] = g_aj[(b * NA + j) * H + h];
    }
    for (int idx = t; idx < KC_IT * H; idx += 256) {
        int ii = idx >> 7, h = idx & 127;
        s.ai[ii * KC_P + h] = g_ai[(b * NA + i0 + ii) * H + h];
    }
    if (t < H) s.w2[t] = ga2_w[t];
    __syncthreads();

    const float eb = ga2_b[0];
    const int j = t, lane = t & 31, wid = t >> 5;
    const float4* ajv = reinterpret_cast<const float4*>(&s.aj[j * KC_P]);
    const float4* w2v = reinterpret_cast<const float4*>(s.w2);

    for (int ii = 0; ii < KC_IT; ii++) {
        const float4* aiv = reinterpret_cast<const float4*>(&s.ai[ii * KC_P]);
        float acc = 0.0f;
#pragma unroll 8
        for (int q = 0; q < H / 4; q++) {
            float4 a4 = aiv[q], j4 = ajv[q], w4 = w2v[q];
            acc = fmaf(fmaxf(a4.x + j4.x, 0.0f), w4.x, acc);
            acc = fmaf(fmaxf(a4.y + j4.y, 0.0f), w4.y, acc);
            acc = fmaf(fmaxf(a4.z + j4.z, 0.0f), w4.z, acc);
            acc = fmaf(fmaxf(a4.w + j4.w, 0.0f), w4.w, acc);
        }
        float e = acc + eb;
        if (adj[(i0 + ii) * NA + j] == 0.0f) e = -1e9f;
        // block softmax over 256 j
        float m = e;
#pragma unroll
        for (int o = 16; o; o >>= 1) m = fmaxf(m, __shfl_xor_sync(0xffffffffu, m, o));
        if (lane == 0) s.redm[wid] = m;
        __syncthreads();
        float mm = s.redm[0];
#pragma unroll
        for (int w = 1; w < 8; w++) mm = fmaxf(mm, s.redm[w]);
        float p  = expf(e - mm);
        float ss = p;
#pragma unroll
        for (int o = 16; o; o >>= 1) ss += __shfl_xor_sync(0xffffffffu, ss, o);
        if (lane == 0) s.reds[wid] = ss;
        __syncthreads();
        float tot = 0.0f;
#pragma unroll
        for (int w = 0; w < 8; w++) tot += s.reds[w];
        g_aw[(b * NA + i0 + ii) * NA + j] = p / tot;
        __syncthreads();
    }
}

// ============================================================================
// K4: h_prime = aw@hg ; comm = h_prime@gout^T + b ; q = [agg, comm]@fc2^T + b
// One (batch, 16-i-tile) per block, 128 threads.
// ============================================================================
constexpr int KD_IT = 16;
constexpr int KD_P  = 20;   // hpT pitch
constexpr int KD_CP = 132;  // commS pitch

__global__ __launch_bounds__(128)
void k_out(const float* __restrict__ gout_w, const float* __restrict__ gout_b,
           const float* __restrict__ fc2_w, const float* __restrict__ fc2_b,
           float* __restrict__ out)
{
    __shared__ float awT[NA * KD_IT];        // [j][ii] pitch 16
    __shared__ float hpT[H * KD_P];          // [h][ii]
    __shared__ float commS[KD_IT * KD_CP];   // [ii][o]
    const int t  = threadIdx.x;
    const int b  = blockIdx.y;
    const int i0 = blockIdx.x * KD_IT;

    for (int idx = t; idx < NA * KD_IT; idx += 128) {
        int j = idx >> 4, ii = idx & 15;
        awT[j * KD_IT + ii] = g_aw[(b * NA + i0 + ii) * NA + j];
    }
    __syncthreads();

    // h_prime[ii][h=t] = sum_j aw[ii][j] * hg[j][t]
    {
        unsigned long long acc[KD_IT / 2];
#pragma unroll
        for (int q = 0; q < KD_IT / 2; q++) acc[q] = 0ull;
        const float* hgp = g_hg + b * NA * H + t;
#pragma unroll 4
        for (int j = 0; j < NA; j++) {
            float v = hgp[j * H];
            unsigned long long vv = pk2(v, v);
            const ulonglong2* ap = reinterpret_cast<const ulonglong2*>(&awT[j * KD_IT]);
            ulonglong2 a0 = ap[0], a1 = ap[1];
            acc[0] = f2fma(a0.x, vv, acc[0]);
            acc[1] = f2fma(a0.y, vv, acc[1]);
            acc[2] = f2fma(a1.x, vv, acc[2]);
            acc[3] = f2fma(a1.y, vv, acc[3]);
            ap += 2;
            ulonglong2 a2 = ap[0], a3 = ap[1];
            acc[4] = f2fma(a2.x, vv, acc[4]);
            acc[5] = f2fma(a2.y, vv, acc[5]);
            acc[6] = f2fma(a3.x, vv, acc[6]);
            acc[7] = f2fma(a3.y, vv, acc[7]);
        }
#pragma unroll
        for (int q = 0; q < KD_IT / 2; q++) {
            float2 f = up2(acc[q]);
            hpT[t * KD_P + 2 * q]     = f.x;
            hpT[t * KD_P + 2 * q + 1] = f.y;
        }
    }
    __syncthreads();

    // comm[ii][o=t] = sum_h h_prime[ii][h] * gout_w[o][h] + gout_b[o]
    {
        unsigned long long acc[KD_IT / 2];
#pragma unroll
        for (int q = 0; q < KD_IT / 2; q++) acc[q] = 0ull;
        const float* wr = gout_w + t * H;
#pragma unroll 1
        for (int h = 0; h < H; h += 4) {
            float4 w4 = *reinterpret_cast<const float4*>(wr + h);
            gemv_step<KD_IT>(&hpT[(h + 0) * KD_P], w4.x, acc);
            gemv_step<KD_IT>(&hpT[(h + 1) * KD_P], w4.y, acc);
            gemv_step<KD_IT>(&hpT[(h + 2) * KD_P], w4.z, acc);
            gemv_step<KD_IT>(&hpT[(h + 3) * KD_P], w4.w, acc);
        }
        float bias = gout_b[t];
#pragma unroll
        for (int q = 0; q < KD_IT / 2; q++) {
            float2 f = up2(acc[q]);
            commS[(2 * q) * KD_CP + t]     = f.x + bias;
            commS[(2 * q + 1) * KD_CP + t] = f.y + bias;
        }
    }
    __syncthreads();

    // q[ii][a]: thread t -> (ii = t>>3, a = t&7)
    {
        const int ii = t >> 3, a = t & 7;
        const float* aggp = g_agg + (b * NA + i0 + ii) * H;
        const float* w    = fc2_w + a * (2 * H);
        const float* cp   = &commS[ii * KD_CP];
        float acc = fc2_b[a];
#pragma unroll 4
        for (int h = 0; h < H; h++) acc = fmaf(aggp[h], w[h], acc);
#pragma unroll 4
        for (int h = 0; h < H; h++) acc = fmaf(cp[h], w[H + h], acc);
        out[(b * NA + i0 + ii) * NACT + a] = acc;
    }
}

// ============================================================================
extern "C" void kernel_launch(void* const* d_in, const int* in_sizes, int n_in,
                              void* d_out, int out_size)
{
    const float* lf     = (const float*)d_in[0];
    const float* hid    = (const float*)d_in[1];
    const float* adj    = (const float*)d_in[2];
    const float* fc1_w  = (const float*)d_in[3];
    const float* fc1_b  = (const float*)d_in[4];
    const float* w_ih   = (const float*)d_in[5];
    const float* w_hh   = (const float*)d_in[6];
    const float* b_ih   = (const float*)d_in[7];
    const float* b_hh   = (const float*)d_in[8];
    const float* law    = (const float*)d_in[9];
    const float* lab    = (const float*)d_in[10];
    const float* gfc_w  = (const float*)d_in[11];
    const float* gfc_b  = (const float*)d_in[12];
    const float* ga1_w  = (const float*)d_in[13];
    const float* ga1_b  = (const float*)d_in[14];
    const float* ga2_w  = (const float*)d_in[15];
    const float* ga2_b  = (const float*)d_in[16];
    const float* gout_w = (const float*)d_in[17];
    const float* gout_b = (const float*)d_in[18];
    const float* fc2_w  = (const float*)d_in[19];
    const float* fc2_b  = (const float*)d_in[20];
    float* out = (float*)d_out;

    const int k1_smem = (int)sizeof(KAS);
    const int k3_smem = (int)sizeof(KCS);
    cudaFuncSetAttribute(k_lane, cudaFuncAttributeMaxDynamicSharedMemorySize, k1_smem);
    cudaFuncSetAttribute(k_edge, cudaFuncAttributeMaxDynamicSharedMemorySize, k3_smem);

    k_lane<<<BN / KA_BNPB, KA_T, k1_smem>>>(lf, hid, fc1_w, fc1_b, w_ih, w_hh,
                                            b_ih, b_hh, law, lab);
    k_graphproj<<<BN / KB_R, 128>>>(gfc_w, gfc_b, ga1_w, ga1_b);
    k_edge<<<dim3(NA / KC_IT, NB), 256, k3_smem>>>(adj, ga2_w, ga2_b);
    k_out<<<dim3(NA / KD_IT, NB), 128>>>(gout_w, gout_b, fc2_w, fc2_b, out);
}

// round 4
// speedup vs baseline: 1.0590x; 1.0590x over previous
#include <cuda_runtime.h>
#include <cuda_bf16.h>

#define DEVI static __device__ __forceinline__

// ---------------- problem dims ----------------
constexpr int BN   = 2048;   // BS * N_AGENTS
constexpr int LN   = 12;     // MAX_LANES
constexpr int LD   = 27;     // LANE_DIM
constexpr int H    = 128;    // HID
constexpr int NB   = 8;      // BS
constexpr int NA   = 256;    // N_AGENTS
constexpr int NACT = 8;
constexpr int G3   = 3 * H;  // 384

// ---------------- scratch (no cudaMalloc allowed) ----------------
__device__ float g_agg[BN * H];
__device__ float g_hg [BN * H];
__device__ float g_ai [BN * H];   // a_i with ga1_b folded in
__device__ float g_aj [BN * H];

// ---------------- packed f32x2 helpers ----------------
DEVI unsigned long long pk2(float a, float b) {
    unsigned long long r;
    asm("mov.b64 %0, {%1, %2};" : "=l"(r) : "f"(a), "f"(b));
    return r;
}
DEVI unsigned long long f2fma(unsigned long long a, unsigned long long b, unsigned long long c) {
    unsigned long long d;
    asm("fma.rn.f32x2 %0, %1, %2, %3;" : "=l"(d) : "l"(a), "l"(b), "l"(c));
    return d;
}
DEVI float2 up2(unsigned long long v) {
    float lo, hi;
    asm("mov.b64 {%0, %1}, %2;" : "=f"(lo), "=f"(hi) : "l"(v));
    return make_float2(lo, hi);
}

// acc[NR/2] packed pairs over NR rows; xrow = transposed activations, 16B aligned
template<int NR>
DEVI void gemv_step(const float* __restrict__ xrow, float w, unsigned long long* acc) {
    unsigned long long ww = pk2(w, w);
    const ulonglong2* xp = reinterpret_cast<const ulonglong2*>(xrow);
#pragma unroll
    for (int q = 0; q < NR / 4; q++) {
        ulonglong2 xv = xp[q];
        acc[2 * q]     = f2fma(xv.x, ww, acc[2 * q]);
        acc[2 * q + 1] = f2fma(xv.y, ww, acc[2 * q + 1]);
    }
}

DEVI float sigm(float x) { return 1.0f / (1.0f + expf(-x)); }

// ============================================================================
// K1: lane encoder. 4 agents (48 lane-rows) per block, 384 threads.
// fc1+relu -> gi (and gh unless h_in tile is all-zero) -> GRU gates ->
// lane-attention softmax -> aggregated (BN,H)
// ============================================================================
constexpr int KA_BNPB = 4;
constexpr int KA_R    = KA_BNPB * LN;   // 48
constexpr int KA_T    = 384;

struct KAS {
    float lf[KA_R][28];      //   5376 B
    float xT[H][KA_R];       //  24576 B  (x transposed; later overwritten with h)
    float hinT[H][KA_R];     //  24576 B
    float gi[KA_R][G3];      //  73728 B
    float gh[KA_R][G3];      //  73728 B
    float sc[KA_R];
    float ps[KA_R];
};

__global__ __launch_bounds__(KA_T, 1)
void k_lane(const float* __restrict__ lf, const float* __restrict__ hid,
            const float* __restrict__ fc1_w, const float* __restrict__ fc1_b,
            const float* __restrict__ w_ih, const float* __restrict__ w_hh,
            const float* __restrict__ b_ih, const float* __restrict__ b_hh,
            const float* __restrict__ law, const float* __restrict__ lab)
{
    extern __shared__ float smem_raw[];
    KAS& s = *reinterpret_cast<KAS*>(smem_raw);
    const int t  = threadIdx.x;
    const int R0 = blockIdx.x * KA_R;   // global lane-row base

    for (int idx = t; idx < KA_R * LD; idx += KA_T) {
        int r = idx / LD, d = idx % LD;
        s.lf[r][d] = lf[(R0 + r) * LD + d];
    }
    bool nz = false;
    for (int idx = t; idx < KA_R * H; idx += KA_T) {
        int r = idx >> 7, h = idx & 127;
        float v = hid[(R0 + r) * H + h];
        nz |= (v != 0.0f);
        s.hinT[h][r] = v;
    }
    const int any = __syncthreads_or((int)nz);

    // x = relu(lf @ fc1^T + b)  -> xT[h][r]
    for (int idx = t; idx < H * KA_R; idx += KA_T) {
        int h = idx / KA_R, r = idx % KA_R;
        float acc = fc1_b[h];
        const float* wr = fc1_w + h * LD;
#pragma unroll
        for (int d = 0; d < LD; d++) acc += s.lf[r][d] * wr[d];
        s.xT[h][r] = fmaxf(acc, 0.0f);
    }
    __syncthreads();

    // gi = x @ w_ih^T : thread t = gate-row g, all 48 rows live in packed regs
    {
        const int g = t;
        unsigned long long acc[KA_R / 2];
#pragma unroll
        for (int q = 0; q < KA_R / 2; q++) acc[q] = 0ull;
        const float* wr = w_ih + g * H;
#pragma unroll 2
        for (int h = 0; h < H; h += 4) {
            float4 w4 = *reinterpret_cast<const float4*>(wr + h);
            gemv_step<KA_R>(&s.xT[h + 0][0], w4.x, acc);
            gemv_step<KA_R>(&s.xT[h + 1][0], w4.y, acc);
            gemv_step<KA_R>(&s.xT[h + 2][0], w4.z, acc);
            gemv_step<KA_R>(&s.xT[h + 3][0], w4.w, acc);
        }
#pragma unroll
        for (int q = 0; q < KA_R / 2; q++) {
            float2 f = up2(acc[q]);
            s.gi[2 * q][g]     = f.x;
            s.gi[2 * q + 1][g] = f.y;
        }
    }
    // gh = h_in @ w_hh^T — skipped when this block's h_in tile is all-zero
    if (any) {
        const int g = t;
        unsigned long long acc[KA_R / 2];
#pragma unroll
        for (int q = 0; q < KA_R / 2; q++) acc[q] = 0ull;
        const float* wr = w_hh + g * H;
#pragma unroll 2
        for (int h = 0; h < H; h += 4) {
            float4 w4 = *reinterpret_cast<const float4*>(wr + h);
            gemv_step<KA_R>(&s.hinT[h + 0][0], w4.x, acc);
            gemv_step<KA_R>(&s.hinT[h + 1][0], w4.y, acc);
            gemv_step<KA_R>(&s.hinT[h + 2][0], w4.z, acc);
            gemv_step<KA_R>(&s.hinT[h + 3][0], w4.w, acc);
        }
#pragma unroll
        for (int q = 0; q < KA_R / 2; q++) {
            float2 f = up2(acc[q]);
            s.gh[2 * q][g]     = f.x;
            s.gh[2 * q + 1][g] = f.y;
        }
    }
    __syncthreads();

    // GRU gates -> h (stored over xT)
    for (int idx = t; idx < KA_R * H; idx += KA_T) {
        int r = idx >> 7, h = idx & 127;
        float gir = s.gi[r][h]         + b_ih[h];
        float giz = s.gi[r][H + h]     + b_ih[H + h];
        float gin = s.gi[r][2 * H + h] + b_ih[2 * H + h];
        float ghr = b_hh[h], ghz = b_hh[H + h], ghn = b_hh[2 * H + h];
        if (any) {
            ghr += s.gh[r][h];
            ghz += s.gh[r][H + h];
            ghn += s.gh[r][2 * H + h];
        }
        float rr = sigm(gir + ghr);
        float zz = sigm(giz + ghz);
        float nn = tanhf(gin + rr * ghn);
        s.xT[h][r] = (1.0f - zz) * nn + zz * s.hinT[h][r];
    }
    __syncthreads();

    // lane-attention scores: warp w handles rows 4w..4w+3 (155-dim dot, shuffle reduce)
    {
        const int wid = t >> 5, lane = t & 31;
        const float lb = lab[0];
        for (int r = wid * 4; r < wid * 4 + 4; r++) {
            float acc = 0.0f;
            if (lane < LD) acc = s.lf[r][lane] * law[lane];
#pragma unroll
            for (int h = lane; h < H; h += 32) acc += s.xT[h][r] * law[LD + h];
#pragma unroll
            for (int o = 16; o; o >>= 1) acc += __shfl_xor_sync(0xffffffffu, acc, o);
            if (lane == 0) s.sc[r] = acc + lb;
        }
    }
    __syncthreads();
    if (t < KA_R) {
        int bl = t / LN;
        float m = -1e30f;
#pragma unroll
        for (int l = 0; l < LN; l++) m = fmaxf(m, s.sc[bl * LN + l]);
        float sum = 0.0f;
#pragma unroll
        for (int l = 0; l < LN; l++) sum += expf(s.sc[bl * LN + l] - m);
        s.ps[t] = expf(s.sc[t] - m) / sum;
    }
    __syncthreads();
    // aggregated[h] = sum_l p_l * h[l][h]
    for (int idx = t; idx < KA_BNPB * H; idx += KA_T) {
        int bl = idx >> 7, h = idx & 127;
        float acc = 0.0f;
#pragma unroll
        for (int l = 0; l < LN; l++) acc += s.ps[bl * LN + l] * s.xT[h][bl * LN + l];
        g_agg[(blockIdx.x * KA_BNPB + bl) * H + h] = acc;
    }
}

// ============================================================================
// K2: hg = agg@gfc^T + b ; a_i = hg@A^T + ga1_b ; a_j = hg@B^T
// 16 agent-rows per block, 128 threads (thread = output channel)
// ============================================================================
constexpr int KB_R = 16;

__global__ __launch_bounds__(128)
void k_graphproj(const float* __restrict__ gfc_w, const float* __restrict__ gfc_b,
                 const float* __restrict__ ga1_w, const float* __restrict__ ga1_b)
{
    __shared__ float aggT[H][KB_R];
    __shared__ float hgT[H][KB_R];
    const int t  = threadIdx.x;
    const int r0 = blockIdx.x * KB_R;

    for (int idx = t; idx < KB_R * H; idx += 128) {
        int r = idx >> 7, h = idx & 127;
        aggT[h][r] = g_agg[(r0 + r) * H + h];
    }
    __syncthreads();
    {
        unsigned long long acc[KB_R / 2];
#pragma unroll
        for (int q = 0; q < KB_R / 2; q++) acc[q] = 0ull;
        const float* wr = gfc_w + t * H;
#pragma unroll 2
        for (int h = 0; h < H; h += 4) {
            float4 w4 = *reinterpret_cast<const float4*>(wr + h);
            gemv_step<KB_R>(&aggT[h + 0][0], w4.x, acc);
            gemv_step<KB_R>(&aggT[h + 1][0], w4.y, acc);
            gemv_step<KB_R>(&aggT[h + 2][0], w4.z, acc);
            gemv_step<KB_R>(&aggT[h + 3][0], w4.w, acc);
        }
        float bias = gfc_b[t];
#pragma unroll
        for (int q = 0; q < KB_R / 2; q++) {
            float2 f = up2(acc[q]);
            float v0 = f.x + bias, v1 = f.y + bias;
            hgT[t][2 * q]     = v0;
            hgT[t][2 * q + 1] = v1;
            g_hg[(r0 + 2 * q) * H + t]     = v0;
            g_hg[(r0 + 2 * q + 1) * H + t] = v1;
        }
    }
    __syncthreads();
    {
        unsigned long long accA[KB_R / 2], accB[KB_R / 2];
#pragma unroll
        for (int q = 0; q < KB_R / 2; q++) { accA[q] = 0ull; accB[q] = 0ull; }
        const float* wa = ga1_w + t * (2 * H);
        const float* wb = wa + H;
#pragma unroll 2
        for (int h = 0; h < H; h += 4) {
            float4 a4 = *reinterpret_cast<const float4*>(wa + h);
            float4 b4 = *reinterpret_cast<const float4*>(wb + h);
            gemv_step<KB_R>(&hgT[h + 0][0], a4.x, accA);
            gemv_step<KB_R>(&hgT[h + 0][0], b4.x, accB);
            gemv_step<KB_R>(&hgT[h + 1][0], a4.y, accA);
            gemv_step<KB_R>(&hgT[h + 1][0], b4.y, accB);
            gemv_step<KB_R>(&hgT[h + 2][0], a4.z, accA);
            gemv_step<KB_R>(&hgT[h + 2][0], b4.z, accB);
            gemv_step<KB_R>(&hgT[h + 3][0], a4.w, accA);
            gemv_step<KB_R>(&hgT[h + 3][0], b4.w, accB);
        }
        float ba = ga1_b[t];
#pragma unroll
        for (int q = 0; q < KB_R / 2; q++) {
            float2 fa = up2(accA[q]);
            float2 fb = up2(accB[q]);
            g_ai[(r0 + 2 * q) * H + t]     = fa.x + ba;
            g_ai[(r0 + 2 * q + 1) * H + t] = fa.y + ba;
            g_aj[(r0 + 2 * q) * H + t]     = fb.x;
            g_aj[(r0 + 2 * q + 1) * H + t] = fb.y;
        }
    }
}

// ============================================================================
// K3 (fused GAT): edge scores + masked softmax + h_prime + comm + q head.
// Block = (batch b, 16-row i-tile), 256 threads. aw never leaves smem.
// ============================================================================
constexpr int KC_IT = 16;
constexpr int KC_P  = 132;   // float pitch for [*][H] tiles (33 float4s, conflict-free)
constexpr int KC_SP = 257;   // float pitch for [ii][NA] score rows

struct KCS {
    float slab[NA * KC_P];     // ajS [j][h], later reused as hgS [j][h]   135168 B
    float tile[KC_IT * KC_P];  // aiS [ii][h], later reused as hpS [ii][h]   8448 B
    float aw[KC_IT * KC_SP];   // scores -> softmax weights                 16448 B
    float commS[KC_IT * KC_P]; //                                            8448 B
    float w2[H];               //                                             512 B
};

__global__ __launch_bounds__(256, 1)
void k_gat(const float* __restrict__ adj, const float* __restrict__ ga2_w,
           const float* __restrict__ ga2_b,
           const float* __restrict__ gout_w, const float* __restrict__ gout_b,
           const float* __restrict__ fc2_w, const float* __restrict__ fc2_b,
           float* __restrict__ out)
{
    extern __shared__ float smem_raw[];
    KCS& s = *reinterpret_cast<KCS*>(smem_raw);
    const int t  = threadIdx.x;
    const int b  = blockIdx.y;
    const int i0 = blockIdx.x * KC_IT;
    float4* slab4 = reinterpret_cast<float4*>(s.slab);
    float4* tile4 = reinterpret_cast<float4*>(s.tile);

    // ---- Phase A: load aj slab (coalesced float4), ai tile, w2 ----
    {
        const float4* src = reinterpret_cast<const float4*>(g_aj + b * NA * H);
#pragma unroll
        for (int k = 0; k < NA * (H / 4) / 256; k++) {
            int idx = t + 256 * k;          // j = idx>>5, q = idx&31
            int j = idx >> 5, q = idx & 31;
            slab4[j * 33 + q] = src[idx];
        }
        const float4* asrc = reinterpret_cast<const float4*>(g_ai + (b * NA + i0) * H);
        for (int idx = t; idx < KC_IT * (H / 4); idx += 256) {
            int ii = idx >> 5, q = idx & 31;
            tile4[ii * 33 + q] = asrc[idx];
        }
        if (t < H) s.w2[t] = ga2_w[t];
    }
    __syncthreads();

    // ---- Phase B: scores. thread = j; aj row register-cached in 32-h chunks ----
    {
        const int j = t;
        float acc[KC_IT];
#pragma unroll
        for (int ii = 0; ii < KC_IT; ii++) acc[ii] = 0.0f;
        const float4* w2v = reinterpret_cast<const float4*>(s.w2);
#pragma unroll
        for (int hc = 0; hc < 4; hc++) {
            float4 ajv[8], w4r[8];
#pragma unroll
            for (int u = 0; u < 8; u++) {
                ajv[u] = slab4[j * 33 + hc * 8 + u];
                w4r[u] = w2v[hc * 8 + u];
            }
#pragma unroll
            for (int ii = 0; ii < KC_IT; ii++) {
                float a = 0.0f;
#pragma unroll
                for (int u = 0; u < 8; u++) {
                    float4 ai4 = tile4[ii * 33 + hc * 8 + u];
                    a = fmaf(fmaxf(ai4.x + ajv[u].x, 0.0f), w4r[u].x, a);
                    a = fmaf(fmaxf(ai4.y + ajv[u].y, 0.0f), w4r[u].y, a);
                    a = fmaf(fmaxf(ai4.z + ajv[u].z, 0.0f), w4r[u].z, a);
                    a = fmaf(fmaxf(ai4.w + ajv[u].w, 0.0f), w4r[u].w, a);
                }
                acc[ii] += a;
            }
        }
        const float eb = ga2_b[0];
#pragma unroll
        for (int ii = 0; ii < KC_IT; ii++) {
            float e = acc[ii] + eb;
            if (adj[(i0 + ii) * NA + j] == 0.0f) e = -1e9f;
            s.aw[ii * KC_SP + j] = e;
        }
    }
    __syncthreads();

    // ---- Phase C: softmax over j, warp-private (warp w owns rows w and w+8) ----
    {
        const int wid = t >> 5, lane = t & 31;
#pragma unroll
        for (int rr2 = 0; rr2 < 2; rr2++) {
            int ii = rr2 * 8 + wid;
            float v[8];
            float m = -1e30f;
#pragma unroll
            for (int sdx = 0; sdx < 8; sdx++) {
                v[sdx] = s.aw[ii * KC_SP + lane + 32 * sdx];
                m = fmaxf(m, v[sdx]);
            }
#pragma unroll
            for (int o = 16; o; o >>= 1) m = fmaxf(m, __shfl_xor_sync(0xffffffffu, m, o));
            float ssum = 0.0f;
#pragma unroll
            for (int sdx = 0; sdx < 8; sdx++) {
                v[sdx] = expf(v[sdx] - m);
                ssum += v[sdx];
            }
#pragma unroll
            for (int o = 16; o; o >>= 1) ssum += __shfl_xor_sync(0xffffffffu, ssum, o);
            float inv = 1.0f / ssum;
#pragma unroll
            for (int sdx = 0; sdx < 8; sdx++)
                s.aw[ii * KC_SP + lane + 32 * sdx] = v[sdx] * inv;
        }
    }
    __syncthreads();

    // ---- Phase D: stage hg[b] into slab (overwrites ajS) ----
    {
        const float4* src = reinterpret_cast<const float4*>(g_hg + b * NA * H);
#pragma unroll
        for (int k = 0; k < NA * (H / 4) / 256; k++) {
            int idx = t + 256 * k;
            int j = idx >> 5, q = idx & 31;
            slab4[j * 33 + q] = src[idx];
        }
    }
    __syncthreads();

    // ---- Phase E: h_prime[ii][h] = sum_j aw[ii][j] * hg[j][h] ----
    {
        const int h = t & 127, half = t >> 7, ii0 = half * 8;
        unsigned long long acc[4];
#pragma unroll
        for (int q = 0; q < 4; q++) acc[q] = 0ull;
#pragma unroll 2
        for (int j = 0; j < NA; j++) {
            float hv = s.slab[j * KC_P + h];
            unsigned long long hh = pk2(hv, hv);
#pragma unroll
            for (int q = 0; q < 4; q++) {
                unsigned long long aa = pk2(s.aw[(ii0 + 2 * q) * KC_SP + j],
                                            s.aw[(ii0 + 2 * q + 1) * KC_SP + j]);
                acc[q] = f2fma(hh, aa, acc[q]);
            }
        }
#pragma unroll
        for (int q = 0; q < 4; q++) {
            float2 f = up2(acc[q]);
            s.tile[(ii0 + 2 * q) * KC_P + h]     = f.x;   // hpS (aiS is dead)
            s.tile[(ii0 + 2 * q + 1) * KC_P + h] = f.y;
        }
    }
    __syncthreads();

    // ---- Phase F: comm[ii][o] = h_prime[ii] . gout_w[o] + gout_b[o] (t<128) ----
    if (t < H) {
        const int o = t;
        unsigned long long acc[KC_IT / 2];
#pragma unroll
        for (int q = 0; q < KC_IT / 2; q++) acc[q] = 0ull;
        const float* wr = gout_w + o * H;
#pragma unroll 2
        for (int h = 0; h < H; h += 4) {
            float4 w4 = *reinterpret_cast<const float4*>(wr + h);
#pragma unroll
            for (int q = 0; q < KC_IT / 2; q++) {
                unsigned long long p0 = pk2(s.tile[(2 * q) * KC_P + h],     s.tile[(2 * q + 1) * KC_P + h]);
                unsigned long long p1 = pk2(s.tile[(2 * q) * KC_P + h + 1], s.tile[(2 * q + 1) * KC_P + h + 1]);
                unsigned long long p2 = pk2(s.tile[(2 * q) * KC_P + h + 2], s.tile[(2 * q + 1) * KC_P + h + 2]);
                unsigned long long p3 = pk2(s.tile[(2 * q) * KC_P + h + 3], s.tile[(2 * q + 1) * KC_P + h + 3]);
                acc[q] = f2fma(p0, pk2(w4.x, w4.x), acc[q]);
                acc[q] = f2fma(p1, pk2(w4.y, w4.y), acc[q]);
                acc[q] = f2fma(p2, pk2(w4.z, w4.z), acc[q]);
                acc[q] = f2fma(p3, pk2(w4.w, w4.w), acc[q]);
            }
        }
        float bias = gout_b[o];
#pragma unroll
        for (int q = 0; q < KC_IT / 2; q++) {
            float2 f = up2(acc[q]);
            s.commS[(2 * q) * KC_P + o]     = f.x + bias;
            s.commS[(2 * q + 1) * KC_P + o] = f.y + bias;
        }
    }
    __syncthreads();

    // ---- Phase G: q[ii][a] = [agg; comm] . fc2[a] + b (t<128) ----
    if (t < 128) {
        const int ii = t >> 3, a = t & 7;
        const float* aggp = g_agg + (b * NA + i0 + ii) * H;
        const float* w    = fc2_w + a * (2 * H);
        const float* cp   = &s.commS[ii * KC_P];
        float acc = fc2_b[a];
#pragma unroll 4
        for (int h = 0; h < H; h++) acc = fmaf(aggp[h], w[h], acc);
#pragma unroll 4
        for (int h = 0; h < H; h++) acc = fmaf(cp[h], w[H + h], acc);
        out[(b * NA + i0 + ii) * NACT + a] = acc;
    }
}

// ============================================================================
extern "C" void kernel_launch(void* const* d_in, const int* in_sizes, int n_in,
                              void* d_out, int out_size)
{
    const float* lf     = (const float*)d_in[0];
    const float* hid    = (const float*)d_in[1];
    const float* adj    = (const float*)d_in[2];
    const float* fc1_w  = (const float*)d_in[3];
    const float* fc1_b  = (const float*)d_in[4];
    const float* w_ih   = (const float*)d_in[5];
    const float* w_hh   = (const float*)d_in[6];
    const float* b_ih   = (const float*)d_in[7];
    const float* b_hh   = (const float*)d_in[8];
    const float* law    = (const float*)d_in[9];
    const float* lab    = (const float*)d_in[10];
    const float* gfc_w  = (const float*)d_in[11];
    const float* gfc_b  = (const float*)d_in[12];
    const float* ga1_w  = (const float*)d_in[13];
    const float* ga1_b  = (const float*)d_in[14];
    const float* ga2_w  = (const float*)d_in[15];
    const float* ga2_b  = (const float*)d_in[16];
    const float* gout_w = (const float*)d_in[17];
    const float* gout_b = (const float*)d_in[18];
    const float* fc2_w  = (const float*)d_in[19];
    const float* fc2_b  = (const float*)d_in[20];
    float* out = (float*)d_out;

    const int k1_smem = (int)sizeof(KAS);
    const int k3_smem = (int)sizeof(KCS);
    cudaFuncSetAttribute(k_lane, cudaFuncAttributeMaxDynamicSharedMemorySize, k1_smem);
    cudaFuncSetAttribute(k_gat,  cudaFuncAttributeMaxDynamicSharedMemorySize, k3_smem);

    k_lane<<<BN / KA_BNPB, KA_T, k1_smem>>>(lf, hid, fc1_w, fc1_b, w_ih, w_hh,
                                            b_ih, b_hh, law, lab);
    k_graphproj<<<BN / KB_R, 128>>>(gfc_w, gfc_b, ga1_w, ga1_b);
    k_gat<<<dim3(NA / KC_IT, NB), 256, k3_smem>>>(adj, ga2_w, ga2_b,
                                                  gout_w, gout_b, fc2_w, fc2_b, out);
}

// round 13
// speedup vs baseline: 1.2727x; 1.2019x over previous
#include <cuda_runtime.h>
#include <cuda_bf16.h>

#define DEVI static __device__ __forceinline__

// ---------------- problem dims ----------------
constexpr int BN   = 2048;   // BS * N_AGENTS
constexpr int LN   = 12;     // MAX_LANES
constexpr int LD   = 27;     // LANE_DIM
constexpr int H    = 128;    // HID
constexpr int NB   = 8;      // BS
constexpr int NA   = 256;    // N_AGENTS
constexpr int NACT = 8;
constexpr int G3   = 3 * H;  // 384

// ---------------- scratch (no cudaMalloc allowed) ----------------
__device__ float g_agg[BN * H];
__device__ float g_hg [BN * H];
__device__ float g_ai [BN * H];   // a_i with ga1_b folded in
__device__ float g_aj [BN * H];
__device__ float g_wihT[H * G3];  // w_ih transposed: [h][g] for coalesced loads
__device__ float g_whhT[H * G3];  // w_hh transposed: [h][g]

// ---------------- packed f32x2 helpers ----------------
DEVI unsigned long long pk2(float a, float b) {
    unsigned long long r;
    asm("mov.b64 %0, {%1, %2};" : "=l"(r) : "f"(a), "f"(b));
    return r;
}
DEVI unsigned long long f2fma(unsigned long long a, unsigned long long b, unsigned long long c) {
    unsigned long long d;
    asm("fma.rn.f32x2 %0, %1, %2, %3;" : "=l"(d) : "l"(a), "l"(b), "l"(c));
    return d;
}
DEVI float2 up2(unsigned long long v) {
    float lo, hi;
    asm("mov.b64 {%0, %1}, %2;" : "=f"(lo), "=f"(hi) : "l"(v));
    return make_float2(lo, hi);
}

DEVI float sigm(float x) { return 1.0f / (1.0f + expf(-x)); }

// ============================================================================
// K0: transpose GRU weights [g][h] -> [h][g] (coalesced reads in k_lane).
// Runs once per launch, ordered before k_lane by stream semantics.
// ============================================================================
__global__ __launch_bounds__(256)
void k_prep(const float* __restrict__ w_ih, const float* __restrict__ w_hh)
{
    int idx = blockIdx.x * 256 + threadIdx.x;   // idx = g*H + h, coalesced read
    if (idx < G3 * H) {
        int g = idx / H, h = idx % H;
        g_wihT[h * G3 + g] = w_ih[idx];
        g_whhT[h * G3 + g] = w_hh[idx];
    }
}

// ============================================================================
// K1: lane encoder. 4 agents (48 lane-rows) per block, 384 threads.
// GEMMs: warp = 16-row block (broadcast LDS), thread = 3 gate columns,
// weights from the transposed layout (fully coalesced LDG.32).
// ============================================================================
constexpr int KA_BNPB = 4;
constexpr int KA_R    = KA_BNPB * LN;   // 48
constexpr int KA_T    = 384;
constexpr int KA_P    = 50;             // xT/hinT pitch: even (8B pairs), 2-way max conflict

struct KAS {
    float lf[KA_R][28];      //   5376 B
    float xT[H][KA_P];       //  25600 B  (x transposed; later overwritten with h)
    float hinT[H][KA_P];     //  25600 B
    float gi[KA_R][G3];      //  73728 B
    float gh[KA_R][G3];      //  73728 B
    float sc[KA_R];
    float ps[KA_R];
};

// warp-uniform-rows GEMM step: 16 rows (8 packed pairs) x 3 gates.
// wT layout [h][g]: lane-consecutive g => coalesced weight loads.
DEVI void wu_gemm3(const float* __restrict__ wT, int g0, const float (*xT)[KA_P],
                   int rb, unsigned long long acc[3][8]) {
#pragma unroll 1
    for (int h = 0; h < H; h += 4) {
        float w[4][3];
#pragma unroll
        for (int hh = 0; hh < 4; hh++) {
#pragma unroll
            for (int u = 0; u < 3; u++)
                w[hh][u] = wT[(h + hh) * G3 + g0 + 32 * u];
        }
#pragma unroll
        for (int hh = 0; hh < 4; hh++) {
            const unsigned long long* xv =
                reinterpret_cast<const unsigned long long*>(&xT[h + hh][rb * 16]);
            unsigned long long pA = pk2(w[hh][0], w[hh][0]);
            unsigned long long pB = pk2(w[hh][1], w[hh][1]);
            unsigned long long pC = pk2(w[hh][2], w[hh][2]);
#pragma unroll
            for (int p = 0; p < 8; p++) {
                unsigned long long x = xv[p];
                acc[0][p] = f2fma(x, pA, acc[0][p]);
                acc[1][p] = f2fma(x, pB, acc[1][p]);
                acc[2][p] = f2fma(x, pC, acc[2][p]);
            }
        }
    }
}

__global__ __launch_bounds__(KA_T, 1)
void k_lane(const float* __restrict__ lf, const float* __restrict__ hid,
            const float* __restrict__ fc1_w, const float* __restrict__ fc1_b,
            const float* __restrict__ b_ih, const float* __restrict__ b_hh,
            const float* __restrict__ law, const float* __restrict__ lab)
{
    extern __shared__ float smem_raw[];
    KAS& s = *reinterpret_cast<KAS*>(smem_raw);
    const int t  = threadIdx.x;
    const int R0 = blockIdx.x * KA_R;   // global lane-row base

    for (int idx = t; idx < KA_R * LD; idx += KA_T) {
        int r = idx / LD, d = idx % LD;
        s.lf[r][d] = lf[(R0 + r) * LD + d];
    }
    bool nz = false;
    for (int idx = t; idx < KA_R * H; idx += KA_T) {
        int r = idx >> 7, h = idx & 127;
        float v = hid[(R0 + r) * H + h];
        nz |= (v != 0.0f);
        s.hinT[h][r] = v;
    }
    const int any = __syncthreads_or((int)nz);

    // x = relu(lf @ fc1^T + b)  -> xT[h][r]
    for (int idx = t; idx < H * KA_R; idx += KA_T) {
        int h = idx / KA_R, r = idx % KA_R;
        float acc = fc1_b[h];
        const float* wr = fc1_w + h * LD;
#pragma unroll
        for (int d = 0; d < LD; d++) acc += s.lf[r][d] * wr[d];
        s.xT[h][r] = fmaxf(acc, 0.0f);
    }
    __syncthreads();

    // warp tiling: rb = 16-row block (warp-uniform), g0 = first of 3 gate cols
    const int wid = t >> 5, lane = t & 31;
    const int rb = wid % 3;
    const int g0 = (wid / 3) * 96 + lane;

    // gi = x @ w_ih^T
    {
        unsigned long long acc[3][8];
#pragma unroll
        for (int u = 0; u < 3; u++)
#pragma unroll
            for (int p = 0; p < 8; p++) acc[u][p] = 0ull;
        wu_gemm3(g_wihT, g0, s.xT, rb, acc);
#pragma unroll
        for (int u = 0; u < 3; u++) {
            int g = g0 + 32 * u;
#pragma unroll
            for (int p = 0; p < 8; p++) {
                float2 f = up2(acc[u][p]);
                s.gi[rb * 16 + 2 * p][g]     = f.x;
                s.gi[rb * 16 + 2 * p + 1][g] = f.y;
            }
        }
    }
    // gh = h_in @ w_hh^T — skipped when this block's h_in tile is all-zero
    if (any) {
        unsigned long long acc[3][8];
#pragma unroll
        for (int u = 0; u < 3; u++)
#pragma unroll
            for (int p = 0; p < 8; p++) acc[u][p] = 0ull;
        wu_gemm3(g_whhT, g0, s.hinT, rb, acc);
#pragma unroll
        for (int u = 0; u < 3; u++) {
            int g = g0 + 32 * u;
#pragma unroll
            for (int p = 0; p < 8; p++) {
                float2 f = up2(acc[u][p]);
                s.gh[rb * 16 + 2 * p][g]     = f.x;
                s.gh[rb * 16 + 2 * p + 1][g] = f.y;
            }
        }
    }
    __syncthreads();

    // GRU gates -> h (stored over xT)
    for (int idx = t; idx < KA_R * H; idx += KA_T) {
        int r = idx >> 7, h = idx & 127;
        float gir = s.gi[r][h]         + b_ih[h];
        float giz = s.gi[r][H + h]     + b_ih[H + h];
        float gin = s.gi[r][2 * H + h] + b_ih[2 * H + h];
        float ghr = b_hh[h], ghz = b_hh[H + h], ghn = b_hh[2 * H + h];
        if (any) {
            ghr += s.gh[r][h];
            ghz += s.gh[r][H + h];
            ghn += s.gh[r][2 * H + h];
        }
        float rr = sigm(gir + ghr);
        float zz = sigm(giz + ghz);
        float nn = tanhf(gin + rr * ghn);
        s.xT[h][r] = (1.0f - zz) * nn + zz * s.hinT[h][r];
    }
    __syncthreads();

    // lane-attention scores: warp w handles rows 4w..4w+3 (155-dim dot, shuffle reduce)
    {
        const float lb = lab[0];
        for (int r = wid * 4; r < wid * 4 + 4; r++) {
            float acc = 0.0f;
            if (lane < LD) acc = s.lf[r][lane] * law[lane];
#pragma unroll
            for (int h = lane; h < H; h += 32) acc += s.xT[h][r] * law[LD + h];
#pragma unroll
            for (int o = 16; o; o >>= 1) acc += __shfl_xor_sync(0xffffffffu, acc, o);
            if (lane == 0) s.sc[r] = acc + lb;
        }
    }
    __syncthreads();
    if (t < KA_R) {
        int bl = t / LN;
        float m = -1e30f;
#pragma unroll
        for (int l = 0; l < LN; l++) m = fmaxf(m, s.sc[bl * LN + l]);
        float sum = 0.0f;
#pragma unroll
        for (int l = 0; l < LN; l++) sum += expf(s.sc[bl * LN + l] - m);
        s.ps[t] = expf(s.sc[t] - m) / sum;
    }
    __syncthreads();
    // aggregated[h] = sum_l p_l * h[l][h]
    for (int idx = t; idx < KA_BNPB * H; idx += KA_T) {
        int bl = idx >> 7, h = idx & 127;
        float acc = 0.0f;
#pragma unroll
        for (int l = 0; l < LN; l++) acc += s.ps[bl * LN + l] * s.xT[h][bl * LN + l];
        g_agg[(blockIdx.x * KA_BNPB + bl) * H + h] = acc;
    }
}

// ============================================================================
// K2: hg = agg@gfc^T + b ; a_i = hg@A^T + ga1_b ; a_j = hg@B^T
// 16 agent-rows per block, 128 threads. Warp = 4-row block (broadcast LDS),
// thread = 4 gate columns (A and B streams in the second GEMM).
// ============================================================================
constexpr int KB_R = 16;
constexpr int KB_P = 18;   // pitch: even, 2-way max conflict

__global__ __launch_bounds__(128)
void k_graphproj(const float* __restrict__ gfc_w, const float* __restrict__ gfc_b,
                 const float* __restrict__ ga1_w, const float* __restrict__ ga1_b)
{
    __shared__ float aggT[H][KB_P];
    __shared__ float hgT[H][KB_P];
    const int t  = threadIdx.x;
    const int r0 = blockIdx.x * KB_R;
    const int wid = t >> 5, lane = t & 31;

    for (int idx = t; idx < KB_R * H; idx += 128) {
        int r = idx >> 7, h = idx & 127;
        aggT[h][r] = g_agg[(r0 + r) * H + h];
    }
    __syncthreads();

    // hg: warp wid -> rows 4*wid..4*wid+3 (2 pairs), thread -> gates lane+32u
    {
        unsigned long long acc[4][2];
#pragma unroll
        for (int u = 0; u < 4; u++) { acc[u][0] = 0ull; acc[u][1] = 0ull; }
        const float* w0 = gfc_w + lane * H;
#pragma unroll 1
        for (int h = 0; h < H; h += 4) {
            float4 w4[4];
#pragma unroll
            for (int u = 0; u < 4; u++)
                w4[u] = *reinterpret_cast<const float4*>(w0 + u * 32 * H + h);
#pragma unroll
            for (int hh = 0; hh < 4; hh++) {
                const unsigned long long* xv =
                    reinterpret_cast<const unsigned long long*>(&aggT[h + hh][wid * 4]);
                unsigned long long x0 = xv[0], x1 = xv[1];
#pragma unroll
                for (int u = 0; u < 4; u++) {
                    float wv = (&w4[u].x)[hh];
                    unsigned long long pw = pk2(wv, wv);
                    acc[u][0] = f2fma(x0, pw, acc[u][0]);
                    acc[u][1] = f2fma(x1, pw, acc[u][1]);
                }
            }
        }
#pragma unroll
        for (int u = 0; u < 4; u++) {
            int g = lane + 32 * u;
            float bias = gfc_b[g];
#pragma unroll
            for (int p = 0; p < 2; p++) {
                float2 f = up2(acc[u][p]);
                int r = wid * 4 + 2 * p;
                hgT[g][r]     = f.x + bias;
                hgT[g][r + 1] = f.y + bias;
                g_hg[(r0 + r) * H + g]     = f.x + bias;
                g_hg[(r0 + r + 1) * H + g] = f.y + bias;
            }
        }
    }
    __syncthreads();

    // a_i / a_j: same tiling, 8 weight streams (4 A + 4 B)
    {
        unsigned long long accA[4][2], accB[4][2];
#pragma unroll
        for (int u = 0; u < 4; u++) {
            accA[u][0] = accA[u][1] = 0ull;
            accB[u][0] = accB[u][1] = 0ull;
        }
        const float* wbase = ga1_w + lane * (2 * H);
#pragma unroll 1
        for (int h = 0; h < H; h += 4) {
            float4 wa4[4], wb4[4];
#pragma unroll
            for (int u = 0; u < 4; u++) {
                wa4[u] = *reinterpret_cast<const float4*>(wbase + u * 32 * (2 * H) + h);
                wb4[u] = *reinterpret_cast<const float4*>(wbase + u * 32 * (2 * H) + H + h);
            }
#pragma unroll
            for (int hh = 0; hh < 4; hh++) {
                const unsigned long long* xv =
                    reinterpret_cast<const unsigned long long*>(&hgT[h + hh][wid * 4]);
                unsigned long long x0 = xv[0], x1 = xv[1];
#pragma unroll
                for (int u = 0; u < 4; u++) {
                    float wa = (&wa4[u].x)[hh], wb = (&wb4[u].x)[hh];
                    unsigned long long pa = pk2(wa, wa), pb = pk2(wb, wb);
                    accA[u][0] = f2fma(x0, pa, accA[u][0]);
                    accA[u][1] = f2fma(x1, pa, accA[u][1]);
                    accB[u][0] = f2fma(x0, pb, accB[u][0]);
                    accB[u][1] = f2fma(x1, pb, accB[u][1]);
                }
            }
        }
#pragma unroll
        for (int u = 0; u < 4; u++) {
            int g = lane + 32 * u;
            float ba = ga1_b[g];
#pragma unroll
            for (int p = 0; p < 2; p++) {
                float2 fa = up2(accA[u][p]);
                float2 fb = up2(accB[u][p]);
                int r = wid * 4 + 2 * p;
                g_ai[(r0 + r) * H + g]     = fa.x + ba;
                g_ai[(r0 + r + 1) * H + g] = fa.y + ba;
                g_aj[(r0 + r) * H + g]     = fb.x;
                g_aj[(r0 + r + 1) * H + g] = fb.y;
            }
        }
    }
}

// ============================================================================
// K3 (fused GAT): edge scores + masked softmax + h_prime + comm + q head.
// Block = (batch b, 16-row i-tile), 256 threads. aw never leaves smem.
// ============================================================================
constexpr int KC_IT = 16;
constexpr int KC_P  = 132;   // float pitch for [*][H] tiles (33 float4s, conflict-free)
constexpr int KC_SP = 257;   // float pitch for [ii][NA] score rows

struct KCS {
    float slab[NA * KC_P];     // ajS [j][h], later reused as hgS [j][h]   135168 B
    float tile[KC_IT * KC_P];  // aiS [ii][h], later reused as hpS [ii][h]   8448 B
    float aw[KC_IT * KC_SP];   // scores -> softmax weights                 16448 B
    float commS[KC_IT * KC_P]; //                                            8448 B
    float w2[H];               //                                             512 B
};

__global__ __launch_bounds__(256, 1)
void k_gat(const float* __restrict__ adj, const float* __restrict__ ga2_w,
           const float* __restrict__ ga2_b,
           const float* __restrict__ gout_w, const float* __restrict__ gout_b,
           const float* __restrict__ fc2_w, const float* __restrict__ fc2_b,
           float* __restrict__ out)
{
    extern __shared__ float smem_raw[];
    KCS& s = *reinterpret_cast<KCS*>(smem_raw);
    const int t  = threadIdx.x;
    const int b  = blockIdx.y;
    const int i0 = blockIdx.x * KC_IT;
    float4* slab4 = reinterpret_cast<float4*>(s.slab);
    float4* tile4 = reinterpret_cast<float4*>(s.tile);

    // ---- Phase A: load aj slab (coalesced float4), ai tile, w2 ----
    {
        const float4* src = reinterpret_cast<const float4*>(g_aj + b * NA * H);
#pragma unroll
        for (int k = 0; k < NA * (H / 4) / 256; k++) {
            int idx = t + 256 * k;          // j = idx>>5, q = idx&31
            int j = idx >> 5, q = idx & 31;
            slab4[j * 33 + q] = src[idx];
        }
        const float4* asrc = reinterpret_cast<const float4*>(g_ai + (b * NA + i0) * H);
        for (int idx = t; idx < KC_IT * (H / 4); idx += 256) {
            int ii = idx >> 5, q = idx & 31;
            tile4[ii * 33 + q] = asrc[idx];
        }
        if (t < H) s.w2[t] = ga2_w[t];
    }
    __syncthreads();

    // ---- Phase B: scores. thread = j; aj row register-cached in 32-h chunks ----
    {
        const int j = t;
        float acc[KC_IT];
#pragma unroll
        for (int ii = 0; ii < KC_IT; ii++) acc[ii] = 0.0f;
        const float4* w2v = reinterpret_cast<const float4*>(s.w2);
#pragma unroll
        for (int hc = 0; hc < 4; hc++) {
            float4 ajv[8], w4r[8];
#pragma unroll
            for (int u = 0; u < 8; u++) {
                ajv[u] = slab4[j * 33 + hc * 8 + u];
                w4r[u] = w2v[hc * 8 + u];
            }
#pragma unroll
            for (int ii = 0; ii < KC_IT; ii++) {
                float a = 0.0f;
#pragma unroll
                for (int u = 0; u < 8; u++) {
                    float4 ai4 = tile4[ii * 33 + hc * 8 + u];
                    a = fmaf(fmaxf(ai4.x + ajv[u].x, 0.0f), w4r[u].x, a);
                    a = fmaf(fmaxf(ai4.y + ajv[u].y, 0.0f), w4r[u].y, a);
                    a = fmaf(fmaxf(ai4.z + ajv[u].z, 0.0f), w4r[u].z, a);
                    a = fmaf(fmaxf(ai4.w + ajv[u].w, 0.0f), w4r[u].w, a);
                }
                acc[ii] += a;
            }
        }
        const float eb = ga2_b[0];
#pragma unroll
        for (int ii = 0; ii < KC_IT; ii++) {
            float e = acc[ii] + eb;
            if (adj[(i0 + ii) * NA + j] == 0.0f) e = -1e9f;
            s.aw[ii * KC_SP + j] = e;
        }
    }
    __syncthreads();

    // ---- Phase C: softmax over j, warp-private (warp w owns rows w and w+8) ----
    {
        const int wid = t >> 5, lane = t & 31;
#pragma unroll
        for (int rr2 = 0; rr2 < 2; rr2++) {
            int ii = rr2 * 8 + wid;
            float v[8];
            float m = -1e30f;
#pragma unroll
            for (int sdx = 0; sdx < 8; sdx++) {
                v[sdx] = s.aw[ii * KC_SP + lane + 32 * sdx];
                m = fmaxf(m, v[sdx]);
            }
#pragma unroll
            for (int o = 16; o; o >>= 1) m = fmaxf(m, __shfl_xor_sync(0xffffffffu, m, o));
            float ssum = 0.0f;
#pragma unroll
            for (int sdx = 0; sdx < 8; sdx++) {
                v[sdx] = expf(v[sdx] - m);
                ssum += v[sdx];
            }
#pragma unroll
            for (int o = 16; o; o >>= 1) ssum += __shfl_xor_sync(0xffffffffu, ssum, o);
            float inv = 1.0f / ssum;
#pragma unroll
            for (int sdx = 0; sdx < 8; sdx++)
                s.aw[ii * KC_SP + lane + 32 * sdx] = v[sdx] * inv;
        }
    }
    __syncthreads();

    // ---- Phase D: stage hg[b] into slab (overwrites ajS) ----
    {
        const float4* src = reinterpret_cast<const float4*>(g_hg + b * NA * H);
#pragma unroll
        for (int k = 0; k < NA * (H / 4) / 256; k++) {
            int idx = t + 256 * k;
            int j = idx >> 5, q = idx & 31;
            slab4[j * 33 + q] = src[idx];
        }
    }
    __syncthreads();

    // ---- Phase E: h_prime[ii][h] = sum_j aw[ii][j] * hg[j][h] ----
    {
        const int h = t & 127, half = t >> 7, ii0 = half * 8;
        unsigned long long acc[4];
#pragma unroll
        for (int q = 0; q < 4; q++) acc[q] = 0ull;
#pragma unroll 2
        for (int j = 0; j < NA; j++) {
            float hv = s.slab[j * KC_P + h];
            unsigned long long hh = pk2(hv, hv);
#pragma unroll
            for (int q = 0; q < 4; q++) {
                unsigned long long aa = pk2(s.aw[(ii0 + 2 * q) * KC_SP + j],
                                            s.aw[(ii0 + 2 * q + 1) * KC_SP + j]);
                acc[q] = f2fma(hh, aa, acc[q]);
            }
        }
#pragma unroll
        for (int q = 0; q < 4; q++) {
            float2 f = up2(acc[q]);
            s.tile[(ii0 + 2 * q) * KC_P + h]     = f.x;   // hpS (aiS is dead)
            s.tile[(ii0 + 2 * q + 1) * KC_P + h] = f.y;
        }
    }
    __syncthreads();

    // ---- Phase F: comm[ii][o] = h_prime[ii] . gout_w[o] + gout_b[o] (t<128) ----
    if (t < H) {
        const int o = t;
        unsigned long long acc[KC_IT / 2];
#pragma unroll
        for (int q = 0; q < KC_IT / 2; q++) acc[q] = 0ull;
        const float* wr = gout_w + o * H;
#pragma unroll 2
        for (int h = 0; h < H; h += 4) {
            float4 w4 = *reinterpret_cast<const float4*>(wr + h);
#pragma unroll
            for (int q = 0; q < KC_IT / 2; q++) {
                unsigned long long p0 = pk2(s.tile[(2 * q) * KC_P + h],     s.tile[(2 * q + 1) * KC_P + h]);
                unsigned long long p1 = pk2(s.tile[(2 * q) * KC_P + h + 1], s.tile[(2 * q + 1) * KC_P + h + 1]);
                unsigned long long p2 = pk2(s.tile[(2 * q) * KC_P + h + 2], s.tile[(2 * q + 1) * KC_P + h + 2]);
                unsigned long long p3 = pk2(s.tile[(2 * q) * KC_P + h + 3], s.tile[(2 * q + 1) * KC_P + h + 3]);
                acc[q] = f2fma(p0, pk2(w4.x, w4.x), acc[q]);
                acc[q] = f2fma(p1, pk2(w4.y, w4.y), acc[q]);
                acc[q] = f2fma(p2, pk2(w4.z, w4.z), acc[q]);
                acc[q] = f2fma(p3, pk2(w4.w, w4.w), acc[q]);
            }
        }
        float bias = gout_b[o];
#pragma unroll
        for (int q = 0; q < KC_IT / 2; q++) {
            float2 f = up2(acc[q]);
            s.commS[(2 * q) * KC_P + o]     = f.x + bias;
            s.commS[(2 * q + 1) * KC_P + o] = f.y + bias;
        }
    }
    __syncthreads();

    // ---- Phase G: q[ii][a] = [agg; comm] . fc2[a] + b (t<128) ----
    if (t < 128) {
        const int ii = t >> 3, a = t & 7;
        const float* aggp = g_agg + (b * NA + i0 + ii) * H;
        const float* w    = fc2_w + a * (2 * H);
        const float* cp   = &s.commS[ii * KC_P];
        float acc = fc2_b[a];
#pragma unroll 4
        for (int h = 0; h < H; h++) acc = fmaf(aggp[h], w[h], acc);
#pragma unroll 4
        for (int h = 0; h < H; h++) acc = fmaf(cp[h], w[H + h], acc);
        out[(b * NA + i0 + ii) * NACT + a] = acc;
    }
}

// ============================================================================
extern "C" void kernel_launch(void* const* d_in, const int* in_sizes, int n_in,
                              void* d_out, int out_size)
{
    const float* lf     = (const float*)d_in[0];
    const float* hid    = (const float*)d_in[1];
    const float* adj    = (const float*)d_in[2];
    const float* fc1_w  = (const float*)d_in[3];
    const float* fc1_b  = (const float*)d_in[4];
    const float* w_ih   = (const float*)d_in[5];
    const float* w_hh   = (const float*)d_in[6];
    const float* b_ih   = (const float*)d_in[7];
    const float* b_hh   = (const float*)d_in[8];
    const float* law    = (const float*)d_in[9];
    const float* lab    = (const float*)d_in[10];
    const float* gfc_w  = (const float*)d_in[11];
    const float* gfc_b  = (const float*)d_in[12];
    const float* ga1_w  = (const float*)d_in[13];
    const float* ga1_b  = (const float*)d_in[14];
    const float* ga2_w  = (const float*)d_in[15];
    const float* ga2_b  = (const float*)d_in[16];
    const float* gout_w = (const float*)d_in[17];
    const float* gout_b = (const float*)d_in[18];
    const float* fc2_w  = (const float*)d_in[19];
    const float* fc2_b  = (const float*)d_in[20];
    float* out = (float*)d_out;

    const int k1_smem = (int)sizeof(KAS);
    const int k3_smem = (int)sizeof(KCS);
    cudaFuncSetAttribute(k_lane, cudaFuncAttributeMaxDynamicSharedMemorySize, k1_smem);
    cudaFuncSetAttribute(k_gat,  cudaFuncAttributeMaxDynamicSharedMemorySize, k3_smem);

    k_prep<<<(G3 * H + 255) / 256, 256>>>(w_ih, w_hh);
    k_lane<<<BN / KA_BNPB, KA_T, k1_smem>>>(lf, hid, fc1_w, fc1_b,
                                            b_ih, b_hh, law, lab);
    k_graphproj<<<BN / KB_R, 128>>>(gfc_w, gfc_b, ga1_w, ga1_b);
    k_gat<<<dim3(NA / KC_IT, NB), 256, k3_smem>>>(adj, ga2_w, ga2_b,
                                                  gout_w, gout_b, fc2_w, fc2_b, out);
}